// round 9
// baseline (speedup 1.0000x reference)
#include <cuda_runtime.h>
#include <math.h>
#include <stdint.h>

#define NN    512
#define MEM   1024
#define KD    1024
#define TM3   3072
#define NINT  128
#define IBASE 384
#define NLVL  5

// ---------------- scratch (static device allocation, allowed) ----------------
__device__ float g_XIp [4 * NN * TM3];      // x @ ioux_w^T, 4 K-slices
__device__ float g_XFp [4 * NINT * MEM];    // x @ fx_w^T,   4 K-slices
__device__ float g_FHp [4 * 640 * MEM];     // h @ fh_w^T,   4 K-slices (padded rows)
__device__ float g_IOUp[8 * 64 * TM3];      // t_lvl @ iouh_w^T, 8 K-slices
__device__ float g_c   [NN * MEM];          // cell states
__device__ float g_h32 [640 * MEM];         // h copy (padded rows for GEMM A)
__device__ float g_t32 [256 * MEM];         // t copy (padded rows for GEMM A)
__device__ int   g_grp_nodes[NLVL][64];
__device__ int   g_grp_start[NLVL][50];

__device__ __forceinline__ float sigm(float v) {
    return __fdividef(1.0f, 1.0f + __expf(-v));
}
__device__ __forceinline__ float ftanh(float v) {
    return 1.0f - __fdividef(2.0f, __expf(2.0f * v) + 1.0f);
}
__device__ __forceinline__ float to_tf32(float x) {
    uint32_t u;
    asm("cvt.rna.tf32.f32 %0, %1;" : "=r"(u) : "f"(x));
    return __uint_as_float(u);
}

// =================== async-copy / mma helpers ================================
__device__ __forceinline__ uint32_t s2u(const void* p) {
    uint32_t a;
    asm("{ .reg .u64 t; cvta.to.shared.u64 t, %1; cvt.u32.u64 %0, t; }"
        : "=r"(a) : "l"(p));
    return a;
}
__device__ __forceinline__ void cpa16(uint32_t dst, const void* src) {
    asm volatile("cp.async.cg.shared.global [%0], [%1], 16;"
                 :: "r"(dst), "l"(src) : "memory");
}
__device__ __forceinline__ void cpa_commit() {
    asm volatile("cp.async.commit_group;" ::: "memory");
}
__device__ __forceinline__ void cpa_wait2() {
    asm volatile("cp.async.wait_group 2;" ::: "memory");
}
__device__ __forceinline__ void cpa_wait1() {
    asm volatile("cp.async.wait_group 1;" ::: "memory");
}
__device__ __forceinline__ void cpa_wait0() {
    asm volatile("cp.async.wait_group 0;" ::: "memory");
}
__device__ __forceinline__ void mma8(float* c, const uint32_t* a, const uint32_t* b) {
    asm volatile(
        "mma.sync.aligned.m16n8k8.row.col.f32.tf32.tf32.f32 "
        "{%0,%1,%2,%3}, {%4,%5,%6,%7}, {%8,%9}, {%0,%1,%2,%3};"
        : "+f"(c[0]), "+f"(c[1]), "+f"(c[2]), "+f"(c[3])
        : "r"(a[0]), "r"(a[1]), "r"(a[2]), "r"(a[3]), "r"(b[0]), "r"(b[1]));
}

// ====== multi-problem tf32 mma.sync split-K GEMM, 3-stage cp.async ==========
struct GP {
    const float* A; const float* B; float* C;
    int N, Klen, slab, nx, ny, nz;
};
#define SMSTRIDE 36
#define KSTRIDE  1024

template<int BM>
__global__ void __launch_bounds__(256) gemm2(GP p0, GP p1)
{
    constexpr int WM = BM / 2;
    constexpr int MF = BM / 32;
    constexpr int ASZ = BM * SMSTRIDE;
    constexpr int BSZ = 128 * SMSTRIDE;
    constexpr int STG = ASZ + BSZ;

    extern __shared__ float sm[];
    uint32_t uA[3], uB[3];
    #pragma unroll
    for (int s = 0; s < 3; s++) {
        uA[s] = s2u(sm + s * STG);
        uB[s] = s2u(sm + s * STG + ASZ);
    }

    int bid = blockIdx.x;
    GP p = p0;
    int t0 = p0.nx * p0.ny * p0.nz;
    if (bid >= t0) { bid -= t0; p = p1; }
    int bx = bid % p.nx;
    int by = (bid / p.nx) % p.ny;
    int bz = bid / (p.nx * p.ny);

    int tid = threadIdx.x;
    int lane = tid & 31, wid = tid >> 5;
    int wm = wid >> 2, wn = wid & 3;
    int gr = lane >> 2, qc = lane & 3;
    int m0 = by * BM, n0 = bx * 128;
    int koff = bz * p.Klen;

    const float* Abase = p.A + (size_t)m0 * KSTRIDE + koff;
    const float* Bbase = p.B + (size_t)n0 * KSTRIDE + koff;
    float* C = p.C + (size_t)bz * p.slab;
    const int NCH = p.Klen >> 5;

    float cacc[MF][4][4];
    #pragma unroll
    for (int i = 0; i < MF; i++)
        #pragma unroll
        for (int j = 0; j < 4; j++)
            #pragma unroll
            for (int e = 0; e < 4; e++) cacc[i][j][e] = 0.f;

    auto load_chunk = [&](int c, int buf) {
        const float* Ap = Abase + c * 32;
        const float* Bp = Bbase + c * 32;
        #pragma unroll
        for (int i = 0; i < BM / 32; i++) {
            int id = tid + i * 256;
            int row = id >> 3, c4 = (id & 7) << 2;
            cpa16(uA[buf] + (row * SMSTRIDE + c4) * 4, Ap + (size_t)row * KSTRIDE + c4);
        }
        #pragma unroll
        for (int i = 0; i < 4; i++) {
            int id = tid + i * 256;
            int row = id >> 3, c4 = (id & 7) << 2;
            cpa16(uB[buf] + (row * SMSTRIDE + c4) * 4, Bp + (size_t)row * KSTRIDE + c4);
        }
        cpa_commit();
    };

    load_chunk(0, 0);
    if (NCH > 1) load_chunk(1, 1);

    for (int c = 0; c < NCH; c++) {
        int buf = c % 3;
        if (c + 2 < NCH) load_chunk(c + 2, (c + 2) % 3);
        int left = NCH - 1 - c;
        if (left >= 2)      cpa_wait2();
        else if (left == 1) cpa_wait1();
        else                cpa_wait0();
        __syncthreads();

        const float* As = sm + buf * STG;
        const float* Bs = sm + buf * STG + ASZ;
        #pragma unroll
        for (int kk = 0; kk < 4; kk++) {
            int k = kk * 8;
            uint32_t b[4][2];
            #pragma unroll
            for (int ni = 0; ni < 4; ni++) {
                int nr = wn * 32 + ni * 8 + gr;
                b[ni][0] = __float_as_uint(Bs[nr * SMSTRIDE + k + qc]);
                b[ni][1] = __float_as_uint(Bs[nr * SMSTRIDE + k + qc + 4]);
            }
            uint32_t a[MF][4];
            #pragma unroll
            for (int mi = 0; mi < MF; mi++) {
                int mr = wm * WM + mi * 16 + gr;
                a[mi][0] = __float_as_uint(As[mr * SMSTRIDE + k + qc]);
                a[mi][1] = __float_as_uint(As[(mr + 8) * SMSTRIDE + k + qc]);
                a[mi][2] = __float_as_uint(As[mr * SMSTRIDE + k + qc + 4]);
                a[mi][3] = __float_as_uint(As[(mr + 8) * SMSTRIDE + k + qc + 4]);
            }
            #pragma unroll
            for (int mi = 0; mi < MF; mi++)
                #pragma unroll
                for (int ni = 0; ni < 4; ni++)
                    mma8(cacc[mi][ni], a[mi], b[ni]);
        }
        __syncthreads();
    }

    #pragma unroll
    for (int mi = 0; mi < MF; mi++)
        #pragma unroll
        for (int ni = 0; ni < 4; ni++) {
            int row = m0 + wm * WM + mi * 16 + gr;
            int col = n0 + wn * 32 + ni * 8 + qc * 2;
            *(float2*)(C + (size_t)row * p.N + col) =
                make_float2(cacc[mi][ni][0], cacc[mi][ni][1]);
            *(float2*)(C + (size_t)(row + 8) * p.N + col) =
                make_float2(cacc[mi][ni][2], cacc[mi][ni][3]);
        }
}

// ---------------- leaves: nodes 0..383 (XI = 4 partial slabs) ----------------
__global__ void leaf_k(float* __restrict__ h,
                       const float* __restrict__ ioux_b,
                       const float* __restrict__ iouh_b)
{
    int node = blockIdx.y;
    int j = blockIdx.x * 256 + threadIdx.x;
    float v0 = 0.f, v1 = 0.f, v2 = 0.f;
    #pragma unroll
    for (int s = 0; s < 4; s++) {
        const float* xi = g_XIp + (size_t)s * (NN * TM3) + (size_t)node * TM3;
        v0 += xi[j]; v1 += xi[MEM + j]; v2 += xi[2 * MEM + j];
    }
    float ig = sigm(v0 + ioux_b[j] + iouh_b[j]);
    float og = sigm(v1 + ioux_b[MEM + j] + iouh_b[MEM + j]);
    float ug = ftanh(v2 + ioux_b[2 * MEM + j] + iouh_b[2 * MEM + j]);
    float cv = ig * ug;
    size_t idx = (size_t)node * MEM + j;
    g_c[idx] = cv;
    float hv = og * ftanh(cv);
    h[idx] = hv;
    g_h32[idx] = to_tf32(hv);
}

// ---------------- one-time grouping by relation (5 threads) ------------------
__global__ void prep_groups(const int* __restrict__ rel_ids)
{
    const int lvl_n0[NLVL]  = {384, 427, 491, 507, 511};
    const int lvl_cnt[NLVL] = { 43,  64,  16,   4,   1};
    int L = threadIdx.x;
    if (L >= NLVL) return;
    int cnt_r[49];
    for (int r = 0; r < 49; r++) cnt_r[r] = 0;
    int n0 = lvl_n0[L], cnt = lvl_cnt[L];
    for (int i = 0; i < cnt; i++) cnt_r[rel_ids[n0 + i]]++;
    int acc = 0;
    for (int r = 0; r < 49; r++) { g_grp_start[L][r] = acc; acc += cnt_r[r]; }
    g_grp_start[L][49] = acc;
    int pos[49];
    for (int r = 0; r < 49; r++) pos[r] = g_grp_start[L][r];
    for (int i = 0; i < cnt; i++) {
        int r = rel_ids[n0 + i];
        g_grp_nodes[L][pos[r]++] = n0 + i - IBASE;
    }
}

// --- t = (child-sum of h) @ Wrel[rel]^T; csum fused; rel==48 is identity -----
__global__ void __launch_bounds__(256) wrel_grp(const float* __restrict__ Wrel,
                                                const float* __restrict__ h,
                                                const int* __restrict__ child_idx,
                                                int lvl)
{
    int r  = blockIdx.y;
    int s0 = g_grp_start[lvl][r];
    int g  = g_grp_start[lvl][r + 1] - s0;
    if (g == 0) return;
    __shared__ float sh[MEM];
    int lane = threadIdx.x & 31, wid = threadIdx.x >> 5;
    int row = blockIdx.x * 8 + wid;
    bool ident = (r == 48);
    float4 w[8];
    if (!ident) {
        const float* W = Wrel + (size_t)r * (MEM * MEM) + (size_t)row * MEM;
        #pragma unroll
        for (int i = 0; i < 8; i++) w[i] = *(const float4*)(W + (i * 32 + lane) * 4);
    }
    for (int j = 0; j < g; j++) {
        int li = g_grp_nodes[lvl][s0 + j];
        int node = li + IBASE;
        const int* ci = child_idx + node * 4;
        int c0 = ci[0], c1 = ci[1], c2 = ci[2], c3 = ci[3];
        {
            int i = threadIdx.x;
            float4 s = make_float4(0.f, 0.f, 0.f, 0.f);
            if (c0 >= 0) { float4 v = ((const float4*)(h + (size_t)c0 * MEM))[i];
                           s.x += v.x; s.y += v.y; s.z += v.z; s.w += v.w; }
            if (c1 >= 0) { float4 v = ((const float4*)(h + (size_t)c1 * MEM))[i];
                           s.x += v.x; s.y += v.y; s.z += v.z; s.w += v.w; }
            if (c2 >= 0) { float4 v = ((const float4*)(h + (size_t)c2 * MEM))[i];
                           s.x += v.x; s.y += v.y; s.z += v.z; s.w += v.w; }
            if (c3 >= 0) { float4 v = ((const float4*)(h + (size_t)c3 * MEM))[i];
                           s.x += v.x; s.y += v.y; s.z += v.z; s.w += v.w; }
            ((float4*)sh)[i] = s;
        }
        __syncthreads();
        float s;
        if (ident) {
            s = sh[row];
        } else {
            s = 0.f;
            #pragma unroll
            for (int i = 0; i < 8; i++) {
                int k4 = (i * 32 + lane) * 4;
                s += w[i].x * sh[k4] + w[i].y * sh[k4 + 1]
                   + w[i].z * sh[k4 + 2] + w[i].w * sh[k4 + 3];
            }
            #pragma unroll
            for (int o = 16; o; o >>= 1) s += __shfl_xor_sync(0xffffffffu, s, o);
        }
        if (lane == 0) g_t32[(size_t)li * MEM + row] = to_tf32(s);
        __syncthreads();
    }
}

// --- fused: fc from children + gates -> h, c (sums all partial slabs) --------
__global__ void cellfc_k(float* __restrict__ h,
                         const int* __restrict__ child_idx,
                         const float* __restrict__ ioux_b,
                         const float* __restrict__ iouh_b,
                         const float* __restrict__ fx_b,
                         const float* __restrict__ fh_b, int n0)
{
    int node = n0 + blockIdx.y;
    int li = node - IBASE;
    int j = blockIdx.x * 256 + threadIdx.x;
    const int* ci = child_idx + node * 4;

    float xf = 0.f;
    #pragma unroll
    for (int s = 0; s < 4; s++)
        xf += g_XFp[(size_t)s * (NINT * MEM) + (size_t)li * MEM + j];
    float base = xf + fx_b[j] + fh_b[j];

    float fc = 0.f;
    #pragma unroll
    for (int k = 0; k < 4; k++) {
        int c = ci[k];
        if (c >= 0) {
            float fh = 0.f;
            #pragma unroll
            for (int s = 0; s < 4; s++)
                fh += g_FHp[(size_t)s * (640 * MEM) + (size_t)c * MEM + j];
            fc += sigm(fh + base) * g_c[(size_t)c * MEM + j];
        }
    }

    float io0 = 0.f, io1 = 0.f, io2 = 0.f;
    #pragma unroll
    for (int s = 0; s < 8; s++) {
        const float* io = g_IOUp + (size_t)s * (64 * TM3) + (size_t)blockIdx.y * TM3;
        io0 += io[j]; io1 += io[MEM + j]; io2 += io[2 * MEM + j];
    }
    float x0 = 0.f, x1 = 0.f, x2 = 0.f;
    #pragma unroll
    for (int s = 0; s < 4; s++) {
        const float* xi = g_XIp + (size_t)s * (NN * TM3) + (size_t)node * TM3;
        x0 += xi[j]; x1 += xi[MEM + j]; x2 += xi[2 * MEM + j];
    }

    float ig = sigm(io0 + x0 + ioux_b[j] + iouh_b[j]);
    float og = sigm(io1 + x1 + ioux_b[MEM + j] + iouh_b[MEM + j]);
    float ug = ftanh(io2 + x2 + ioux_b[2 * MEM + j] + iouh_b[2 * MEM + j]);
    float cv = ig * ug + fc;
    size_t idx = (size_t)node * MEM + j;
    g_c[idx] = cv;
    float hv = og * ftanh(cv);
    h[idx] = hv;
    g_h32[idx] = to_tf32(hv);
}

// ------------------------------- launcher ------------------------------------
extern "C" void kernel_launch(void* const* d_in, const int* in_sizes, int n_in,
                              void* d_out, int out_size)
{
    const float* x       = (const float*)d_in[0];
    const float* Wrel    = (const float*)d_in[1];
    const float* ioux_w  = (const float*)d_in[2];
    const float* ioux_b  = (const float*)d_in[3];
    const float* iouh_w  = (const float*)d_in[4];
    const float* iouh_b  = (const float*)d_in[5];
    const float* fx_w    = (const float*)d_in[6];
    const float* fx_b    = (const float*)d_in[7];
    const float* fh_w    = (const float*)d_in[8];
    const float* fh_b    = (const float*)d_in[9];
    const int*   child_idx = (const int*)d_in[10];
    const int*   rel_ids   = (const int*)d_in[11];
    float* h = (float*)d_out;

    // side stream + events, created once (outside any capture)
    static cudaStream_t s2 = nullptr;
    static cudaEvent_t ev[12];
    if (!s2) {
        cudaStreamCreateWithFlags(&s2, cudaStreamNonBlocking);
        for (int i = 0; i < 12; i++)
            cudaEventCreateWithFlags(&ev[i], cudaEventDisableTiming);
    }
    // ev[0]=start, ev[1]=leaf done, ev[2+L]=h(L) done (L=0..3),
    // ev[7+L]=FH needed by cellfc(L) ready (L=0..4)

    const int SM128 = 3 * (128 + 128) * SMSTRIDE * 4;   // 110592 B
    const int SM64  = 3 * (64 + 128) * SMSTRIDE * 4;    //  82944 B
    cudaFuncSetAttribute(gemm2<128>, cudaFuncAttributeMaxDynamicSharedMemorySize, SM128);
    cudaFuncSetAttribute(gemm2<64>,  cudaFuncAttributeMaxDynamicSharedMemorySize, SM64);

    float *p_XIp, *p_XFp, *p_FHp, *p_IOUp, *p_h32, *p_t32;
    cudaGetSymbolAddress((void**)&p_XIp,  g_XIp);
    cudaGetSymbolAddress((void**)&p_XFp,  g_XFp);
    cudaGetSymbolAddress((void**)&p_FHp,  g_FHp);
    cudaGetSymbolAddress((void**)&p_IOUp, g_IOUp);
    cudaGetSymbolAddress((void**)&p_h32,  g_h32);
    cudaGetSymbolAddress((void**)&p_t32,  g_t32);

    const GP pNone = { nullptr, nullptr, nullptr, 1, 32, 0, 0, 0, 0 };

    prep_groups<<<1, 32>>>(rel_ids);
    cudaEventRecord(ev[0], 0);
    cudaStreamWaitEvent(s2, ev[0], 0);

    // XI on main stream (512x3072, K=1024, split-K x4)
    GP pXI = { x, ioux_w, p_XIp, TM3, 256, NN * TM3, 24, 4, 4 };
    gemm2<128><<<24 * 4 * 4, 256, SM128>>>(pXI, pNone);
    // XF on side stream (128x1024, split-K x4)
    GP pXF = { x + (size_t)IBASE * KD, fx_w, p_XFp, MEM, 256, NINT * MEM, 8, 1, 4 };
    gemm2<128><<<8 * 1 * 4, 256, SM128, s2>>>(pXF, pNone);

    leaf_k<<<dim3(4, 384), 256>>>(h, ioux_b, iouh_b);
    cudaEventRecord(ev[1], 0);

    // FH for leaves on side stream (384x1024, split-K x4), after leaf h ready
    cudaStreamWaitEvent(s2, ev[1], 0);
    GP pFH0 = { p_h32, fh_w, p_FHp, MEM, 256, 640 * MEM, 8, 3, 4 };
    gemm2<128><<<8 * 3 * 4, 256, SM128, s2>>>(pFH0, pNone);
    cudaEventRecord(ev[7], s2);

    const int lvl_n0[NLVL]  = {384, 427, 491, 507, 511};
    const int lvl_cnt[NLVL] = { 43,  64,  16,   4,   1};
    for (int L = 0; L < NLVL; L++) {
        int n0 = lvl_n0[L], cnt = lvl_cnt[L];

        wrel_grp<<<dim3(128, 49), 256>>>(Wrel, h, child_idx, L);

        // IOU(L) = t_lvl @ iouh_w^T  (pad M to 64, split-K x8)
        GP pIOU = { p_t32 + (size_t)(n0 - IBASE) * MEM, iouh_w, p_IOUp,
                    TM3, 128, 64 * TM3, 24, 1, 8 };
        gemm2<64><<<24 * 1 * 8, 256, SM64>>>(pIOU, pNone);

        // cellfc needs FH of this level's children (computed on s2)
        cudaStreamWaitEvent(0, ev[7 + L], 0);
        cellfc_k<<<dim3(4, cnt), 256>>>(h, child_idx, ioux_b, iouh_b, fx_b, fh_b, n0);

        if (L < NLVL - 1) {
            cudaEventRecord(ev[2 + L], 0);
            cudaStreamWaitEvent(s2, ev[2 + L], 0);
            // FH for this level's nodes (pad M to 64, split-K x4) on side stream
            GP pFH = { p_h32 + (size_t)n0 * MEM, fh_w, p_FHp + (size_t)n0 * MEM,
                       MEM, 256, 640 * MEM, 8, 1, 4 };
            gemm2<64><<<8 * 1 * 4, 256, SM64, s2>>>(pFH, pNone);
            cudaEventRecord(ev[8 + L], s2);
        }
    }
}